// round 15
// baseline (speedup 1.0000x reference)
#include <cuda_runtime.h>
#include <cuda_bf16.h>
#include <mma.h>
#include <stdint.h>
#include <math.h>

using namespace nvcuda;

#define TT   512
#define BB   128
#define HH   512
#define CC   32
#define TIN  128
#define NCHN 2048
#define HORZ 96
#define NELEM (TT*BB*HH)

// ---------------- scratch ----------------
__device__ float g_conv[BB*NCHN*TIN];   // (B, 2048, Tin)
__device__ float g_bufA[NELEM];         // X after bn1: (tau, h, b)
__device__ float g_bufB[NELEM];         // mem3:        (tau, h, b)
__device__ __nv_bfloat16 g_Xhi[NELEM];  // mem3 (m = t*BB+b, k) split
__device__ __nv_bfloat16 g_Xlo[NELEM];
__device__ __nv_bfloat16 g_Yhi[NELEM];  // Y = Xhi @ (Aophi+Aoplo)^T (m, n)
__device__ __nv_bfloat16 g_Aophi[HH*HH], g_Aoplo[HH*HH];
__device__ float g_u[HH], g_w2[HH], g_cc[1];
__device__ float g_c1[TT*BB], g_c2[TT*BB];
__device__ float g_wpart[4*BB*TT];
__device__ float g_wsum[BB*TT];
__device__ float g_z[BB*HH];
__device__ float g_sw[BB];
__device__ float g_feat[BB*HH];
__device__ float g_featn[BB*HH];
__device__ float g_chm[NCHN];
__device__ float g_chr[NCHN];

__device__ __forceinline__ void split1(float x, __nv_bfloat16& hi, __nv_bfloat16& lo) {
    hi = __float2bfloat16(x);
    lo = __float2bfloat16(x - __bfloat162float(hi));
}

// ============== conv: 16 channels/block (R13-identical) ==============
__global__ __launch_bounds__(128) void conv_kernel(const float* __restrict__ x,
                            const float* __restrict__ w,
                            const float* __restrict__ cb) {
    __shared__ float xs2[32*136];
    __shared__ float ws4[16*32*4];
    int b  = blockIdx.y;
    int c0 = blockIdx.x * 16;
    int tid = threadIdx.x;

    for (int i = tid; i < 130*32; i += 128) {
        int r = i >> 5, ci = i & 31;
        int tt = r - 1;
        xs2[ci*136 + r] = (tt >= 0 && tt < TIN) ? x[(b*TIN + tt)*CC + ci] : 0.0f;
    }
    for (int i = tid; i < 512; i += 128) {
        int cc = i >> 5, ii = i & 31;
        const float* wp = w + (c0 + cc)*96 + ii*3;
        float* d = ws4 + i*4;
        d[0] = wp[0]; d[1] = wp[1]; d[2] = wp[2]; d[3] = 0.0f;
    }
    __syncthreads();

    int ccq = tid >> 5;
    int t4  = tid & 31;
    int t0  = t4 * 4;

    float acc[4][4];
    #pragma unroll
    for (int c2 = 0; c2 < 4; c2++) {
        float bias = cb[c0 + ccq*4 + c2];
        acc[c2][0] = acc[c2][1] = acc[c2][2] = acc[c2][3] = bias;
    }

    #pragma unroll
    for (int i = 0; i < 32; i++) {
        float4 xa = *(const float4*)&xs2[i*136 + t0];
        float2 xb = *(const float2*)&xs2[i*136 + t0 + 4];
        #pragma unroll
        for (int c2 = 0; c2 < 4; c2++) {
            float4 wv = *(const float4*)&ws4[((ccq*4 + c2)*32 + i)*4];
            acc[c2][0] += wv.x*xa.x + wv.y*xa.y + wv.z*xa.z;
            acc[c2][1] += wv.x*xa.y + wv.y*xa.z + wv.z*xa.w;
            acc[c2][2] += wv.x*xa.z + wv.y*xa.w + wv.z*xb.x;
            acc[c2][3] += wv.x*xa.w + wv.y*xb.x + wv.z*xb.y;
        }
    }
    #pragma unroll
    for (int c2 = 0; c2 < 4; c2++)
        *(float4*)&g_conv[((size_t)b*NCHN + c0 + ccq*4 + c2)*TIN + t0] =
            make_float4(acc[c2][0], acc[c2][1], acc[c2][2], acc[c2][3]);
}

__global__ void chan_stats_kernel() {
    int c = blockIdx.x;
    int tid = threadIdx.x;
    float s = 0.f, sq = 0.f;
    for (int i = tid; i < BB*TIN; i += 256) {
        int b = i >> 7, t = i & 127;
        float v = g_conv[(b*NCHN + c)*TIN + t];
        s += v; sq += v*v;
    }
    __shared__ float ss[256], sqs[256];
    ss[tid] = s; sqs[tid] = sq;
    __syncthreads();
    for (int o = 128; o > 0; o >>= 1) {
        if (tid < o) { ss[tid] += ss[tid+o]; sqs[tid] += sqs[tid+o]; }
        __syncthreads();
    }
    if (tid == 0) {
        float m   = ss[0] * (1.0f/(BB*TIN));
        float var = sqs[0] * (1.0f/(BB*TIN)) - m*m;
        g_chm[c] = m;
        g_chr[c] = rsqrtf(var + 1e-5f);
    }
}

__global__ void bn1t_kernel(const float* __restrict__ g,
                            const float* __restrict__ bb) {
    __shared__ float sm_t[128*33];
    int c = blockIdx.x, bq = blockIdx.y;
    int ts = c >> 9, h = c & 511;
    int tid = threadIdx.x;
    float chm = g_chm[c], chr = g_chr[c], gg = g[c], bo = bb[c];
    int bl = tid >> 2, tq = tid & 3;
    int b = bq*32 + bl;
    const float* src = g_conv + ((size_t)b*NCHN + c)*TIN;
    #pragma unroll
    for (int it = 0; it < 8; it++) {
        int tbase = (tq + it*4)*4;
        float4 v = *(const float4*)(src + tbase);
        sm_t[(tbase+0)*33 + bl] = (v.x - chm) * chr * gg + bo;
        sm_t[(tbase+1)*33 + bl] = (v.y - chm) * chr * gg + bo;
        sm_t[(tbase+2)*33 + bl] = (v.z - chm) * chr * gg + bo;
        sm_t[(tbase+3)*33 + bl] = (v.w - chm) * chr * gg + bo;
    }
    __syncthreads();
    int bl2 = tid & 31, tch = tid >> 5;
    #pragma unroll 8
    for (int it = 0; it < 32; it++) {
        int t = tch*32 + it;
        g_bufA[((size_t)(t*4 + ts)*HH + h)*BB + bq*32 + bl2] = sm_t[t*33 + bl2];
    }
}

__global__ __launch_bounds__(128) void snn_fused_kernel(
        const float* __restrict__ be,  const float* __restrict__ g2a,
        const float* __restrict__ b2a, const float* __restrict__ be2,
        const float* __restrict__ g3a, const float* __restrict__ b3a,
        const float* __restrict__ be3) {
    __shared__ int scnt[2][2][4];
    int tid = threadIdx.x;
    int h = blockIdx.x;
    int warp = tid >> 5, lane = tid & 31;
    float beta1 = fminf(fmaxf(be[h],  0.0f), 0.99f);
    float beta2 = fminf(fmaxf(be2[h], 0.0f), 0.99f);
    float beta3 = fminf(fmaxf(be3[h], 0.0f), 0.99f);
    float g2 = g2a[h], b2 = b2a[h], g3 = g3a[h], b3 = b3a[h];
    const float* src = g_bufA + (size_t)h*BB + tid;
    float* dst       = g_bufB + (size_t)h*BB + tid;
    float mem1 = 0.f, mem2 = 0.f, mem3 = 0.f;

    float cur[4];
    #pragma unroll
    for (int j = 0; j < 4; j++) cur[j] = src[(size_t)j*HH*BB];

    for (int t0 = 0; t0 < TT; t0 += 4) {
        float nxt[4] = {0.f, 0.f, 0.f, 0.f};
        if (t0 + 4 < TT) {
            #pragma unroll
            for (int j = 0; j < 4; j++) nxt[j] = src[(size_t)(t0+4+j)*HH*BB];
        }
        #pragma unroll
        for (int j = 0; j < 4; j++) {
            int t = t0 + j, par = t & 1;
            float reset = (mem1 > 1.0f) ? 1.0f : 0.0f;
            mem1 = beta1*mem1 + cur[j] - reset;
            float s1 = (mem1 > 1.0f) ? 1.0f : 0.0f;
            unsigned bal = __ballot_sync(0xffffffffu, mem1 > 1.0f);
            if (lane == 0) scnt[0][par][warp] = __popc(bal);
            __syncthreads();
            float sq = (float)(scnt[0][par][0] + scnt[0][par][1]
                             + scnt[0][par][2] + scnt[0][par][3]);
            float m    = sq * (1.0f/BB);
            float rstd = rsqrtf(sq*(1.0f/BB) - m*m + 1e-5f);
            float gg = g2*rstd;
            float bo = b2 - m*gg;
            float h2 = s1*gg + bo;

            float reset2 = (mem2 > 1.0f) ? 1.0f : 0.0f;
            mem2 = beta2*mem2 + h2 - reset2;
            float s2 = (mem2 > 1.0f) ? 1.0f : 0.0f;
            bal = __ballot_sync(0xffffffffu, mem2 > 1.0f);
            if (lane == 0) scnt[1][par][warp] = __popc(bal);
            __syncthreads();
            sq = (float)(scnt[1][par][0] + scnt[1][par][1]
                       + scnt[1][par][2] + scnt[1][par][3]);
            m    = sq * (1.0f/BB);
            rstd = rsqrtf(sq*(1.0f/BB) - m*m + 1e-5f);
            gg = g3*rstd;
            bo = b3 - m*gg;
            float h3 = s2*gg + bo;

            float reset3 = (mem3 > 1.0f) ? 1.0f : 0.0f;
            mem3 = beta3*mem3 + h3 - reset3;
            dst[(size_t)t*HH*BB] = mem3;
        }
        #pragma unroll
        for (int j = 0; j < 4; j++) cur[j] = nxt[j];
    }
}

// ============== prep kernels ==============
__global__ void prep_uwc_kernel(const float* __restrict__ wq,
                                const float* __restrict__ bk,
                                const float* __restrict__ wk,
                                const float* __restrict__ bq) {
    int k = blockIdx.x*128 + threadIdx.x;
    float su = 0.f, sw = 0.f;
    for (int n = 0; n < HH; n++) {
        su += wq[n*HH + k] * bk[n];
        sw += wk[n*HH + k] * bq[n];
    }
    g_u[k] = su; g_w2[k] = sw;
    if (blockIdx.x == 0 && threadIdx.x == 0) {
        float c = 0.f;
        for (int n = 0; n < HH; n++) c += bq[n]*bk[n];
        g_cc[0] = c;
    }
}

__global__ void aop_kernel(const float* __restrict__ wq,
                           const float* __restrict__ wk) {
    int k  = blockIdx.x*128 + threadIdx.x;
    int n0 = blockIdx.y*16;
    float acc[16] = {};
    for (int j = 0; j < HH; j++) {
        float a = wq[j*HH + k];
        #pragma unroll
        for (int i = 0; i < 16; i++)
            acc[i] += a * wk[j*HH + n0 + i];
    }
    #pragma unroll
    for (int i = 0; i < 16; i++) {
        __nv_bfloat16 hi, lo;
        split1(acc[i], hi, lo);
        g_Aophi[(n0+i)*HH + k] = hi;
        g_Aoplo[(n0+i)*HH + k] = lo;
    }
}

__global__ __launch_bounds__(256) void xpose_kernel() {
    __shared__ float smt[32][129];
    int t = blockIdx.x, h0 = blockIdx.y*32;
    int tid = threadIdx.x;
    int b = tid & 127, hq = tid >> 7;
    #pragma unroll
    for (int i = 0; i < 16; i++) {
        int hh2 = hq*16 + i;
        smt[hh2][b] = g_bufB[((size_t)t*HH + h0 + hh2)*BB + b];
    }
    __syncthreads();
    int b2 = tid & 127, half = tid >> 7;
    __nv_bfloat16 hi16[16], lo16[16];
    #pragma unroll
    for (int i = 0; i < 16; i++)
        split1(smt[half*16 + i][b2], hi16[i], lo16[i]);
    size_t base = ((size_t)t*BB + b2)*HH + h0 + half*16;
    *(uint4*)&g_Xhi[base]     = *(uint4*)&hi16[0];
    *(uint4*)&g_Xhi[base + 8] = *(uint4*)&hi16[8];
    *(uint4*)&g_Xlo[base]     = *(uint4*)&lo16[0];
    *(uint4*)&g_Xlo[base + 8] = *(uint4*)&lo16[8];
}

__global__ __launch_bounds__(128) void c12_kernel() {
    __shared__ float su[HH], sw[HH];
    int t = blockIdx.x, tid = threadIdx.x;
    for (int i = tid; i < HH; i += 128) { su[i] = g_u[i]; sw[i] = g_w2[i]; }
    __syncthreads();
    float c1 = 0.f, c2 = 0.f;
    const float* src = g_bufB + (size_t)t*HH*BB + tid;
    #pragma unroll 4
    for (int h = 0; h < HH; h++) {
        float v = src[(size_t)h*BB];
        c1 += v * su[h];
        c2 += v * sw[h];
    }
    g_c1[t*BB + tid] = c1;
    g_c2[t*BB + tid] = c2;
}

// ============== wmma GEMM cores ==============
#define LDA16 24
#define LDS   132
#define SM_DYN (128*LDS*4)
#define BUF_AT 12288   // 2-term core phase size (bf16 elems)
#define BUF2   12288   // 1-term paired core phase size (bf16 elems)

typedef wmma::fragment<wmma::matrix_a, 16,16,16, __nv_bfloat16, wmma::row_major> FragA;
typedef wmma::fragment<wmma::matrix_b, 16,16,16, __nv_bfloat16, wmma::col_major> FragB;
typedef wmma::fragment<wmma::accumulator, 16,16,16, float> FragC;

// 2-term core: A hi-only, B hi+lo (R13-identical; used by y_mma)
__device__ __forceinline__ void mma_tile_pre2(
        const __nv_bfloat16* Ahi, size_t sA,
        const __nv_bfloat16* Bhi, const __nv_bfloat16* Blo, size_t sB,
        char* sm, float* stage) {
    int tid = threadIdx.x, wid = tid >> 5;
    int wm = (wid & 1) * 64, wn = (wid >> 1) * 32;
    int isB = tid >> 7;
    int row = tid & 127;
    const __nv_bfloat16* ghi = isB ? (Bhi + (size_t)row*sB) : (Ahi + (size_t)row*sA);
    const __nv_bfloat16* glo = isB ? (Blo + (size_t)row*sB) : (Ahi + (size_t)row*sA);

    FragC acc[4][2];
    #pragma unroll
    for (int i = 0; i < 4; i++)
        #pragma unroll
        for (int j = 0; j < 2; j++)
            wmma::fill_fragment(acc[i][j], 0.0f);

    uint4 ph0 = *(const uint4*)(ghi);
    uint4 ph1 = *(const uint4*)(ghi + 8);
    uint4 pl0, pl1;
    if (isB) { pl0 = *(const uint4*)(glo); pl1 = *(const uint4*)(glo + 8); }

    for (int ck = 0; ck < 32; ck++) {
        __nv_bfloat16* buf = (__nv_bfloat16*)sm + (ck & 1)*BUF_AT;
        __nv_bfloat16* dhi = buf + isB*6144 + row*LDA16;
        *(uint4*)dhi       = ph0;
        *(uint4*)(dhi + 8) = ph1;
        if (isB) {
            *(uint4*)(dhi + 3072)     = pl0;
            *(uint4*)(dhi + 3072 + 8) = pl1;
        }
        __syncthreads();
        if (ck < 31) {
            ph0 = *(const uint4*)(ghi + (ck+1)*16);
            ph1 = *(const uint4*)(ghi + (ck+1)*16 + 8);
            if (isB) {
                pl0 = *(const uint4*)(glo + (ck+1)*16);
                pl1 = *(const uint4*)(glo + (ck+1)*16 + 8);
            }
        }
        __nv_bfloat16* sA_ = buf;
        __nv_bfloat16* sB_ = buf + 6144;
        FragA ah[4];
        #pragma unroll
        for (int i = 0; i < 4; i++)
            wmma::load_matrix_sync(ah[i], sA_ + (wm + i*16)*LDA16, LDA16);
        #pragma unroll
        for (int j = 0; j < 2; j++) {
            FragB bh, bl;
            wmma::load_matrix_sync(bh, sB_ + (wn + j*16)*LDA16, LDA16);
            wmma::load_matrix_sync(bl, sB_ + 3072 + (wn + j*16)*LDA16, LDA16);
            #pragma unroll
            for (int i = 0; i < 4; i++) {
                wmma::mma_sync(acc[i][j], ah[i], bh, acc[i][j]);
                wmma::mma_sync(acc[i][j], ah[i], bl, acc[i][j]);
            }
        }
    }
    __syncthreads();
    #pragma unroll
    for (int i = 0; i < 4; i++)
        #pragma unroll
        for (int j = 0; j < 2; j++)
            wmma::store_matrix_sync(stage + (wm + i*16)*LDS + wn + j*16,
                                    acc[i][j], LDS, wmma::mem_row_major);
    __syncthreads();
}

// 1-term core, 2 chunks per sync (k-order preserved; used by attention)
__device__ __forceinline__ void mma_tile_pre1(
        const __nv_bfloat16* Ahi, size_t sA,
        const __nv_bfloat16* Bhi, size_t sB,
        char* sm, float* stage) {
    int tid = threadIdx.x, wid = tid >> 5;
    int wm = (wid & 1) * 64, wn = (wid >> 1) * 32;
    int isB = tid >> 7;
    int row = tid & 127;
    const __nv_bfloat16* ghi = isB ? (Bhi + (size_t)row*sB) : (Ahi + (size_t)row*sA);

    FragC acc[4][2];
    #pragma unroll
    for (int i = 0; i < 4; i++)
        #pragma unroll
        for (int j = 0; j < 2; j++)
            wmma::fill_fragment(acc[i][j], 0.0f);

    uint4 p0 = *(const uint4*)(ghi);
    uint4 p1 = *(const uint4*)(ghi + 8);
    uint4 p2 = *(const uint4*)(ghi + 16);
    uint4 p3 = *(const uint4*)(ghi + 24);

    for (int ck = 0; ck < 16; ck++) {
        __nv_bfloat16* buf = (__nv_bfloat16*)sm + (ck & 1)*BUF2;
        __nv_bfloat16* d0 = buf + isB*3072 + row*LDA16;
        __nv_bfloat16* d1 = d0 + 6144;
        *(uint4*)d0       = p0;
        *(uint4*)(d0 + 8) = p1;
        *(uint4*)d1       = p2;
        *(uint4*)(d1 + 8) = p3;
        __syncthreads();
        if (ck < 15) {
            const __nv_bfloat16* p = ghi + (ck + 1)*32;
            p0 = *(const uint4*)(p);
            p1 = *(const uint4*)(p + 8);
            p2 = *(const uint4*)(p + 16);
            p3 = *(const uint4*)(p + 24);
        }
        #pragma unroll
        for (int sub = 0; sub < 2; sub++) {
            __nv_bfloat16* sA_ = buf + sub*6144;
            __nv_bfloat16* sB_ = sA_ + 3072;
            FragA ah[4];
            #pragma unroll
            for (int i = 0; i < 4; i++)
                wmma::load_matrix_sync(ah[i], sA_ + (wm + i*16)*LDA16, LDA16);
            #pragma unroll
            for (int j = 0; j < 2; j++) {
                FragB bh;
                wmma::load_matrix_sync(bh, sB_ + (wn + j*16)*LDA16, LDA16);
                #pragma unroll
                for (int i = 0; i < 4; i++)
                    wmma::mma_sync(acc[i][j], ah[i], bh, acc[i][j]);
            }
        }
    }
    __syncthreads();
    #pragma unroll
    for (int i = 0; i < 4; i++)
        #pragma unroll
        for (int j = 0; j < 2; j++)
            wmma::store_matrix_sync(stage + (wm + i*16)*LDS + wn + j*16,
                                    acc[i][j], LDS, wmma::mem_row_major);
    __syncthreads();
}

// ============== Y = Xhi (Aophi+Aoplo)^T, output bf16 hi ==============
__global__ __launch_bounds__(256, 2) void y_mma_kernel() {
    extern __shared__ char sm[];
    float* stage = (float*)sm;
    int n0 = blockIdx.x*128, m0 = blockIdx.y*128;
    int tid = threadIdx.x;

    mma_tile_pre2(g_Xhi + (size_t)m0*HH, HH,
                  g_Aophi + (size_t)n0*HH, g_Aoplo + (size_t)n0*HH, HH,
                  sm, stage);

    int c = tid & 127, rr = tid >> 7;
    for (int r2 = rr; r2 < 128; r2 += 2)
        g_Yhi[(size_t)(m0 + r2)*HH + n0 + c] = __float2bfloat16(stage[r2*LDS + c]);
}

// ============== attention: sigmoid((Yhi.Xhi + c1 + c2 + c0)*s) sums ==========
__global__ __launch_bounds__(256, 2) void attn_mma_kernel() {
    extern __shared__ char sm[];
    float* stage = (float*)sm;
    __shared__ float c1row[128];
    int b  = blockIdx.z;
    int n0 = blockIdx.x * 128;
    int m0 = blockIdx.y * 128;
    int tid = threadIdx.x;

    mma_tile_pre1(g_Yhi + ((size_t)m0*BB + b)*HH, (size_t)BB*HH,
                  g_Xhi + ((size_t)n0*BB + b)*HH, (size_t)BB*HH,
                  sm, stage);

    if (tid < 128) c1row[tid] = g_c1[(m0 + tid)*BB + b];
    __syncthreads();

    const float scale = 0.04419417382415922f;  // 512^-0.5
    if (tid < 128) {
        float c2v = g_c2[(n0 + tid)*BB + b] + g_cc[0];
        float s = 0.f;
        #pragma unroll 4
        for (int rr = 0; rr < 128; rr++) {
            float lg = stage[rr*LDS + tid] + c1row[rr] + c2v;
            s += 1.0f / (1.0f + __expf(-lg*scale));
        }
        g_wpart[blockIdx.y*(BB*TT) + b*TT + n0 + tid] = s;
    }
}

// ============== tails ==============
__global__ void reduce_w_kernel() {
    int i = blockIdx.x*256 + threadIdx.x;
    g_wsum[i] = g_wpart[i] + g_wpart[BB*TT + i]
              + g_wpart[2*BB*TT + i] + g_wpart[3*BB*TT + i];
}

__global__ __launch_bounds__(128) void zsum_kernel() {
    int kq = blockIdx.x, b = blockIdx.y;
    int k = kq*128 + threadIdx.x;
    float acc = 0.f, sw = 0.f;
    const float* wrow = g_wsum + b*TT;
    #pragma unroll 4
    for (int s = 0; s < TT; s++) {
        float w = wrow[s];
        sw += w;
        size_t idx = ((size_t)s*BB + b)*HH + k;
        float xv = __bfloat162float(g_Xhi[idx]) + __bfloat162float(g_Xlo[idx]);
        acc += w * xv;
    }
    g_z[b*HH + k] = acc;
    if (kq == 0 && threadIdx.x == 0) g_sw[b] = sw;
}

__global__ __launch_bounds__(128) void featw_kernel(
        const float* __restrict__ wv, const float* __restrict__ bv) {
    __shared__ float zs[HH];
    int b = blockIdx.y;
    int d = blockIdx.x*128 + threadIdx.x;
    for (int i = threadIdx.x; i < HH; i += 128) zs[i] = g_z[b*HH + i];
    __syncthreads();
    const float* wr = wv + (size_t)d*HH;
    float acc = 0.f;
    #pragma unroll 4
    for (int k = 0; k < HH; k++) acc += zs[k] * wr[k];
    g_feat[b*HH + d] = (acc + g_sw[b]*bv[d]) * (1.0f/TT);
}

__global__ void feat_bn_kernel(const float* __restrict__ g,
                               const float* __restrict__ bb) {
    int d = threadIdx.x;
    float s = 0.f, sq = 0.f;
    for (int b = 0; b < BB; b++) {
        float v = g_feat[b*HH + d];
        s += v; sq += v*v;
    }
    float m = s * (1.0f/BB);
    float rstd = rsqrtf(sq*(1.0f/BB) - m*m + 1e-5f);
    float gg = g[d]*rstd;
    float bo = bb[d] - m*gg;
    for (int b = 0; b < BB; b++)
        g_featn[b*HH + d] = g_feat[b*HH + d]*gg + bo;
}

__global__ void final_lin_kernel(const float* __restrict__ wh,
                                 const float* __restrict__ bh,
                                 float* __restrict__ out) {
    __shared__ float fs[HH];
    int b = blockIdx.x;
    int o = threadIdx.x;
    for (int i = o; i < HH; i += 96) fs[i] = g_featn[b*HH + i];
    __syncthreads();
    float acc = bh[o];
    for (int d = 0; d < HH; d++) acc += fs[d] * wh[o*HH + d];
    out[b*HORZ + o] = acc;
}

// ---------------- launch ------------------------------------------------------
extern "C" void kernel_launch(void* const* d_in, const int* in_sizes, int n_in,
                              void* d_out, int out_size) {
    const float* x        = (const float*)d_in[0];
    const float* conv_w   = (const float*)d_in[1];
    const float* conv_b   = (const float*)d_in[2];
    const float* bn1_g    = (const float*)d_in[3];
    const float* bn1_b    = (const float*)d_in[4];
    const float* beta_enc = (const float*)d_in[5];
    const float* bn2_g    = (const float*)d_in[6];
    const float* bn2_b    = (const float*)d_in[7];
    const float* beta2    = (const float*)d_in[8];
    const float* bn3_g    = (const float*)d_in[9];
    const float* bn3_b    = (const float*)d_in[10];
    const float* beta3    = (const float*)d_in[11];
    const float* wq       = (const float*)d_in[12];
    const float* bq       = (const float*)d_in[13];
    const float* wk       = (const float*)d_in[14];
    const float* bk       = (const float*)d_in[15];
    const float* wv       = (const float*)d_in[16];
    const float* bv       = (const float*)d_in[17];
    const float* bna_g    = (const float*)d_in[18];
    const float* bna_b    = (const float*)d_in[19];
    const float* wh       = (const float*)d_in[20];
    const float* bh       = (const float*)d_in[21];
    float* out = (float*)d_out;

    cudaFuncSetAttribute(y_mma_kernel,    cudaFuncAttributeMaxDynamicSharedMemorySize, SM_DYN);
    cudaFuncSetAttribute(attn_mma_kernel, cudaFuncAttributeMaxDynamicSharedMemorySize, SM_DYN);

    prep_uwc_kernel<<<4, 128>>>(wq, bk, wk, bq);
    aop_kernel<<<dim3(4, 32), 128>>>(wq, wk);

    conv_kernel<<<dim3(NCHN/16, BB), 128>>>(x, conv_w, conv_b);
    chan_stats_kernel<<<NCHN, 256>>>();
    bn1t_kernel<<<dim3(NCHN, 4), 128>>>(bn1_g, bn1_b);

    snn_fused_kernel<<<HH, 128>>>(beta_enc, bn2_g, bn2_b, beta2, bn3_g, bn3_b, beta3);

    xpose_kernel<<<dim3(TT, 16), 256>>>();
    c12_kernel<<<TT, 128>>>();

    y_mma_kernel<<<dim3(4, TT), 256, SM_DYN>>>();
    attn_mma_kernel<<<dim3(TT/128, TT/128, BB), 256, SM_DYN>>>();

    reduce_w_kernel<<<(BB*TT)/256, 256>>>();
    zsum_kernel<<<dim3(4, BB), 128>>>();
    featw_kernel<<<dim3(4, BB), 128>>>(wv, bv);
    feat_bn_kernel<<<1, HH>>>(bna_g, bna_b);
    final_lin_kernel<<<BB, HORZ>>>(wh, bh, out);
}

// round 16
// speedup vs baseline: 1.0607x; 1.0607x over previous
#include <cuda_runtime.h>
#include <cuda_bf16.h>
#include <mma.h>
#include <stdint.h>
#include <math.h>

using namespace nvcuda;

#define TT   512
#define BB   128
#define HH   512
#define CC   32
#define TIN  128
#define NCHN 2048
#define HORZ 96
#define NELEM (TT*BB*HH)

// ---------------- scratch ----------------
__device__ float g_conv[BB*NCHN*TIN];   // (B, 2048, Tin)
__device__ float g_bufA[NELEM];         // X after bn1: (tau, h, b)
__device__ float g_bufB[NELEM];         // mem3:        (tau, h, b)
__device__ __nv_bfloat16 g_Xhi[NELEM];  // mem3 (m = t*BB+b, k) split
__device__ __nv_bfloat16 g_Xlo[NELEM];
__device__ __nv_bfloat16 g_Yhi[NELEM];  // Y = Xhi @ (Aophi+Aoplo)^T (m, n)
__device__ __nv_bfloat16 g_Aophi[HH*HH], g_Aoplo[HH*HH];
__device__ float g_u[HH], g_w2[HH], g_cc[1];
__device__ float g_c1p[16*TT*BB], g_c2p[16*TT*BB];
__device__ float g_c1[TT*BB], g_c2[TT*BB];
__device__ float g_wpart[4*BB*TT];
__device__ float g_wsum[BB*TT];
__device__ float g_z[BB*HH];
__device__ float g_sw[BB];
__device__ float g_feat[BB*HH];
__device__ float g_featn[BB*HH];
__device__ float g_chm[NCHN];
__device__ float g_chr[NCHN];

__device__ __forceinline__ void split1(float x, __nv_bfloat16& hi, __nv_bfloat16& lo) {
    hi = __float2bfloat16(x);
    lo = __float2bfloat16(x - __bfloat162float(hi));
}

// ============== conv: 16 channels/block (R13-identical) ==============
__global__ __launch_bounds__(128) void conv_kernel(const float* __restrict__ x,
                            const float* __restrict__ w,
                            const float* __restrict__ cb) {
    __shared__ float xs2[32*136];
    __shared__ float ws4[16*32*4];
    int b  = blockIdx.y;
    int c0 = blockIdx.x * 16;
    int tid = threadIdx.x;

    for (int i = tid; i < 130*32; i += 128) {
        int r = i >> 5, ci = i & 31;
        int tt = r - 1;
        xs2[ci*136 + r] = (tt >= 0 && tt < TIN) ? x[(b*TIN + tt)*CC + ci] : 0.0f;
    }
    for (int i = tid; i < 512; i += 128) {
        int cc = i >> 5, ii = i & 31;
        const float* wp = w + (c0 + cc)*96 + ii*3;
        float* d = ws4 + i*4;
        d[0] = wp[0]; d[1] = wp[1]; d[2] = wp[2]; d[3] = 0.0f;
    }
    __syncthreads();

    int ccq = tid >> 5;
    int t4  = tid & 31;
    int t0  = t4 * 4;

    float acc[4][4];
    #pragma unroll
    for (int c2 = 0; c2 < 4; c2++) {
        float bias = cb[c0 + ccq*4 + c2];
        acc[c2][0] = acc[c2][1] = acc[c2][2] = acc[c2][3] = bias;
    }

    #pragma unroll
    for (int i = 0; i < 32; i++) {
        float4 xa = *(const float4*)&xs2[i*136 + t0];
        float2 xb = *(const float2*)&xs2[i*136 + t0 + 4];
        #pragma unroll
        for (int c2 = 0; c2 < 4; c2++) {
            float4 wv = *(const float4*)&ws4[((ccq*4 + c2)*32 + i)*4];
            acc[c2][0] += wv.x*xa.x + wv.y*xa.y + wv.z*xa.z;
            acc[c2][1] += wv.x*xa.y + wv.y*xa.z + wv.z*xa.w;
            acc[c2][2] += wv.x*xa.z + wv.y*xa.w + wv.z*xb.x;
            acc[c2][3] += wv.x*xa.w + wv.y*xb.x + wv.z*xb.y;
        }
    }
    #pragma unroll
    for (int c2 = 0; c2 < 4; c2++)
        *(float4*)&g_conv[((size_t)b*NCHN + c0 + ccq*4 + c2)*TIN + t0] =
            make_float4(acc[c2][0], acc[c2][1], acc[c2][2], acc[c2][3]);
}

__global__ void chan_stats_kernel() {
    int c = blockIdx.x;
    int tid = threadIdx.x;
    float s = 0.f, sq = 0.f;
    for (int i = tid; i < BB*TIN; i += 256) {
        int b = i >> 7, t = i & 127;
        float v = g_conv[(b*NCHN + c)*TIN + t];
        s += v; sq += v*v;
    }
    __shared__ float ss[256], sqs[256];
    ss[tid] = s; sqs[tid] = sq;
    __syncthreads();
    for (int o = 128; o > 0; o >>= 1) {
        if (tid < o) { ss[tid] += ss[tid+o]; sqs[tid] += sqs[tid+o]; }
        __syncthreads();
    }
    if (tid == 0) {
        float m   = ss[0] * (1.0f/(BB*TIN));
        float var = sqs[0] * (1.0f/(BB*TIN)) - m*m;
        g_chm[c] = m;
        g_chr[c] = rsqrtf(var + 1e-5f);
    }
}

__global__ void bn1t_kernel(const float* __restrict__ g,
                            const float* __restrict__ bb) {
    __shared__ float sm_t[128*33];
    int c = blockIdx.x, bq = blockIdx.y;
    int ts = c >> 9, h = c & 511;
    int tid = threadIdx.x;
    float chm = g_chm[c], chr = g_chr[c], gg = g[c], bo = bb[c];
    int bl = tid >> 2, tq = tid & 3;
    int b = bq*32 + bl;
    const float* src = g_conv + ((size_t)b*NCHN + c)*TIN;
    #pragma unroll
    for (int it = 0; it < 8; it++) {
        int tbase = (tq + it*4)*4;
        float4 v = *(const float4*)(src + tbase);
        sm_t[(tbase+0)*33 + bl] = (v.x - chm) * chr * gg + bo;
        sm_t[(tbase+1)*33 + bl] = (v.y - chm) * chr * gg + bo;
        sm_t[(tbase+2)*33 + bl] = (v.z - chm) * chr * gg + bo;
        sm_t[(tbase+3)*33 + bl] = (v.w - chm) * chr * gg + bo;
    }
    __syncthreads();
    int bl2 = tid & 31, tch = tid >> 5;
    #pragma unroll 8
    for (int it = 0; it < 32; it++) {
        int t = tch*32 + it;
        g_bufA[((size_t)(t*4 + ts)*HH + h)*BB + bq*32 + bl2] = sm_t[t*33 + bl2];
    }
}

__global__ __launch_bounds__(128) void snn_fused_kernel(
        const float* __restrict__ be,  const float* __restrict__ g2a,
        const float* __restrict__ b2a, const float* __restrict__ be2,
        const float* __restrict__ g3a, const float* __restrict__ b3a,
        const float* __restrict__ be3) {
    __shared__ int scnt[2][2][4];
    int tid = threadIdx.x;
    int h = blockIdx.x;
    int warp = tid >> 5, lane = tid & 31;
    float beta1 = fminf(fmaxf(be[h],  0.0f), 0.99f);
    float beta2 = fminf(fmaxf(be2[h], 0.0f), 0.99f);
    float beta3 = fminf(fmaxf(be3[h], 0.0f), 0.99f);
    float g2 = g2a[h], b2 = b2a[h], g3 = g3a[h], b3 = b3a[h];
    const float* src = g_bufA + (size_t)h*BB + tid;
    float* dst       = g_bufB + (size_t)h*BB + tid;
    float mem1 = 0.f, mem2 = 0.f, mem3 = 0.f;

    float cur[4];
    #pragma unroll
    for (int j = 0; j < 4; j++) cur[j] = src[(size_t)j*HH*BB];

    for (int t0 = 0; t0 < TT; t0 += 4) {
        float nxt[4] = {0.f, 0.f, 0.f, 0.f};
        if (t0 + 4 < TT) {
            #pragma unroll
            for (int j = 0; j < 4; j++) nxt[j] = src[(size_t)(t0+4+j)*HH*BB];
        }
        #pragma unroll
        for (int j = 0; j < 4; j++) {
            int t = t0 + j, par = t & 1;
            float reset = (mem1 > 1.0f) ? 1.0f : 0.0f;
            mem1 = beta1*mem1 + cur[j] - reset;
            float s1 = (mem1 > 1.0f) ? 1.0f : 0.0f;
            unsigned bal = __ballot_sync(0xffffffffu, mem1 > 1.0f);
            if (lane == 0) scnt[0][par][warp] = __popc(bal);
            __syncthreads();
            float sq = (float)(scnt[0][par][0] + scnt[0][par][1]
                             + scnt[0][par][2] + scnt[0][par][3]);
            float m    = sq * (1.0f/BB);
            float rstd = rsqrtf(sq*(1.0f/BB) - m*m + 1e-5f);
            float gg = g2*rstd;
            float bo = b2 - m*gg;
            float h2 = s1*gg + bo;

            float reset2 = (mem2 > 1.0f) ? 1.0f : 0.0f;
            mem2 = beta2*mem2 + h2 - reset2;
            float s2 = (mem2 > 1.0f) ? 1.0f : 0.0f;
            bal = __ballot_sync(0xffffffffu, mem2 > 1.0f);
            if (lane == 0) scnt[1][par][warp] = __popc(bal);
            __syncthreads();
            sq = (float)(scnt[1][par][0] + scnt[1][par][1]
                       + scnt[1][par][2] + scnt[1][par][3]);
            m    = sq * (1.0f/BB);
            rstd = rsqrtf(sq*(1.0f/BB) - m*m + 1e-5f);
            gg = g3*rstd;
            bo = b3 - m*gg;
            float h3 = s2*gg + bo;

            float reset3 = (mem3 > 1.0f) ? 1.0f : 0.0f;
            mem3 = beta3*mem3 + h3 - reset3;
            dst[(size_t)t*HH*BB] = mem3;
        }
        #pragma unroll
        for (int j = 0; j < 4; j++) cur[j] = nxt[j];
    }
}

// ============== prep kernels ==============
__global__ void prep_uwc_kernel(const float* __restrict__ wq,
                                const float* __restrict__ bk,
                                const float* __restrict__ wk,
                                const float* __restrict__ bq) {
    int k = blockIdx.x*128 + threadIdx.x;
    float su = 0.f, sw = 0.f;
    for (int n = 0; n < HH; n++) {
        su += wq[n*HH + k] * bk[n];
        sw += wk[n*HH + k] * bq[n];
    }
    g_u[k] = su; g_w2[k] = sw;
    if (blockIdx.x == 0 && threadIdx.x == 0) {
        float c = 0.f;
        for (int n = 0; n < HH; n++) c += bq[n]*bk[n];
        g_cc[0] = c;
    }
}

__global__ void aop_kernel(const float* __restrict__ wq,
                           const float* __restrict__ wk) {
    int k  = blockIdx.x*128 + threadIdx.x;
    int n0 = blockIdx.y*16;
    float acc[16] = {};
    for (int j = 0; j < HH; j++) {
        float a = wq[j*HH + k];
        #pragma unroll
        for (int i = 0; i < 16; i++)
            acc[i] += a * wk[j*HH + n0 + i];
    }
    #pragma unroll
    for (int i = 0; i < 16; i++) {
        __nv_bfloat16 hi, lo;
        split1(acc[i], hi, lo);
        g_Aophi[(n0+i)*HH + k] = hi;
        g_Aoplo[(n0+i)*HH + k] = lo;
    }
}

// transpose+split, and emit c1/c2 partials for this 32-h chunk
__global__ __launch_bounds__(256) void xpose_kernel() {
    __shared__ float smt[32][129];
    __shared__ float su32[32], sw32[32];
    __shared__ float p1s[2][128], p2s[2][128];
    int t = blockIdx.x, hc = blockIdx.y;
    int h0 = hc*32;
    int tid = threadIdx.x;
    int b = tid & 127, hq = tid >> 7;
    if (tid < 32) { su32[tid] = g_u[h0 + tid]; sw32[tid] = g_w2[h0 + tid]; }
    #pragma unroll
    for (int i = 0; i < 16; i++) {
        int hh2 = hq*16 + i;
        smt[hh2][b] = g_bufB[((size_t)t*HH + h0 + hh2)*BB + b];
    }
    __syncthreads();
    int b2 = tid & 127, half = tid >> 7;
    __nv_bfloat16 hi16[16], lo16[16];
    #pragma unroll
    for (int i = 0; i < 16; i++)
        split1(smt[half*16 + i][b2], hi16[i], lo16[i]);
    size_t base = ((size_t)t*BB + b2)*HH + h0 + half*16;
    *(uint4*)&g_Xhi[base]     = *(uint4*)&hi16[0];
    *(uint4*)&g_Xhi[base + 8] = *(uint4*)&hi16[8];
    *(uint4*)&g_Xlo[base]     = *(uint4*)&lo16[0];
    *(uint4*)&g_Xlo[base + 8] = *(uint4*)&lo16[8];

    // c1/c2 partials over this h-chunk (deterministic order)
    float p1 = 0.f, p2 = 0.f;
    #pragma unroll
    for (int i = 0; i < 16; i++) {
        int hh2 = half*16 + i;
        float v = smt[hh2][b2];
        p1 += v * su32[hh2];
        p2 += v * sw32[hh2];
    }
    p1s[half][b2] = p1;
    p2s[half][b2] = p2;
    __syncthreads();
    if (tid < 128) {
        g_c1p[(size_t)hc*(TT*BB) + t*BB + tid] = p1s[0][tid] + p1s[1][tid];
        g_c2p[(size_t)hc*(TT*BB) + t*BB + tid] = p2s[0][tid] + p2s[1][tid];
    }
}

__global__ void c12red_kernel() {
    int i = blockIdx.x*256 + threadIdx.x;   // TT*BB
    float c1 = 0.f, c2 = 0.f;
    #pragma unroll
    for (int ch = 0; ch < 16; ch++) {
        c1 += g_c1p[(size_t)ch*(TT*BB) + i];
        c2 += g_c2p[(size_t)ch*(TT*BB) + i];
    }
    g_c1[i] = c1;
    g_c2[i] = c2;
}

// ============== wmma GEMM cores ==============
#define LDA16 24
#define LDS   132
#define SM_DYN (128*LDS*4)
#define BUF_AT 12288

typedef wmma::fragment<wmma::matrix_a, 16,16,16, __nv_bfloat16, wmma::row_major> FragA;
typedef wmma::fragment<wmma::matrix_b, 16,16,16, __nv_bfloat16, wmma::col_major> FragB;
typedef wmma::fragment<wmma::accumulator, 16,16,16, float> FragC;

// 2-term core: A hi-only, B hi+lo (R13-identical; used by y_mma)
__device__ __forceinline__ void mma_tile_pre2(
        const __nv_bfloat16* Ahi, size_t sA,
        const __nv_bfloat16* Bhi, const __nv_bfloat16* Blo, size_t sB,
        char* sm, float* stage) {
    int tid = threadIdx.x, wid = tid >> 5;
    int wm = (wid & 1) * 64, wn = (wid >> 1) * 32;
    int isB = tid >> 7;
    int row = tid & 127;
    const __nv_bfloat16* ghi = isB ? (Bhi + (size_t)row*sB) : (Ahi + (size_t)row*sA);
    const __nv_bfloat16* glo = isB ? (Blo + (size_t)row*sB) : (Ahi + (size_t)row*sA);

    FragC acc[4][2];
    #pragma unroll
    for (int i = 0; i < 4; i++)
        #pragma unroll
        for (int j = 0; j < 2; j++)
            wmma::fill_fragment(acc[i][j], 0.0f);

    uint4 ph0 = *(const uint4*)(ghi);
    uint4 ph1 = *(const uint4*)(ghi + 8);
    uint4 pl0, pl1;
    if (isB) { pl0 = *(const uint4*)(glo); pl1 = *(const uint4*)(glo + 8); }

    for (int ck = 0; ck < 32; ck++) {
        __nv_bfloat16* buf = (__nv_bfloat16*)sm + (ck & 1)*BUF_AT;
        __nv_bfloat16* dhi = buf + isB*6144 + row*LDA16;
        *(uint4*)dhi       = ph0;
        *(uint4*)(dhi + 8) = ph1;
        if (isB) {
            *(uint4*)(dhi + 3072)     = pl0;
            *(uint4*)(dhi + 3072 + 8) = pl1;
        }
        __syncthreads();
        if (ck < 31) {
            ph0 = *(const uint4*)(ghi + (ck+1)*16);
            ph1 = *(const uint4*)(ghi + (ck+1)*16 + 8);
            if (isB) {
                pl0 = *(const uint4*)(glo + (ck+1)*16);
                pl1 = *(const uint4*)(glo + (ck+1)*16 + 8);
            }
        }
        __nv_bfloat16* sA_ = buf;
        __nv_bfloat16* sB_ = buf + 6144;
        FragA ah[4];
        #pragma unroll
        for (int i = 0; i < 4; i++)
            wmma::load_matrix_sync(ah[i], sA_ + (wm + i*16)*LDA16, LDA16);
        #pragma unroll
        for (int j = 0; j < 2; j++) {
            FragB bh, bl;
            wmma::load_matrix_sync(bh, sB_ + (wn + j*16)*LDA16, LDA16);
            wmma::load_matrix_sync(bl, sB_ + 3072 + (wn + j*16)*LDA16, LDA16);
            #pragma unroll
            for (int i = 0; i < 4; i++) {
                wmma::mma_sync(acc[i][j], ah[i], bh, acc[i][j]);
                wmma::mma_sync(acc[i][j], ah[i], bl, acc[i][j]);
            }
        }
    }
    __syncthreads();
    #pragma unroll
    for (int i = 0; i < 4; i++)
        #pragma unroll
        for (int j = 0; j < 2; j++)
            wmma::store_matrix_sync(stage + (wm + i*16)*LDS + wn + j*16,
                                    acc[i][j], LDS, wmma::mem_row_major);
    __syncthreads();
}

// 1-term core: single-chunk per sync (R13-identical; used by attention)
__device__ __forceinline__ void mma_tile_pre1(
        const __nv_bfloat16* Ahi, size_t sA,
        const __nv_bfloat16* Bhi, size_t sB,
        char* sm, float* stage) {
    int tid = threadIdx.x, wid = tid >> 5;
    int wm = (wid & 1) * 64, wn = (wid >> 1) * 32;
    int isB = tid >> 7;
    int row = tid & 127;
    const __nv_bfloat16* ghi = isB ? (Bhi + (size_t)row*sB) : (Ahi + (size_t)row*sA);

    FragC acc[4][2];
    #pragma unroll
    for (int i = 0; i < 4; i++)
        #pragma unroll
        for (int j = 0; j < 2; j++)
            wmma::fill_fragment(acc[i][j], 0.0f);

    uint4 ph0 = *(const uint4*)(ghi);
    uint4 ph1 = *(const uint4*)(ghi + 8);

    for (int ck = 0; ck < 32; ck++) {
        __nv_bfloat16* buf = (__nv_bfloat16*)sm + (ck & 1)*BUF_AT;
        __nv_bfloat16* dhi = buf + isB*6144 + row*LDA16;
        *(uint4*)dhi       = ph0;
        *(uint4*)(dhi + 8) = ph1;
        __syncthreads();
        if (ck < 31) {
            ph0 = *(const uint4*)(ghi + (ck+1)*16);
            ph1 = *(const uint4*)(ghi + (ck+1)*16 + 8);
        }
        __nv_bfloat16* sA_ = buf;
        __nv_bfloat16* sB_ = buf + 6144;
        FragA ah[4];
        #pragma unroll
        for (int i = 0; i < 4; i++)
            wmma::load_matrix_sync(ah[i], sA_ + (wm + i*16)*LDA16, LDA16);
        #pragma unroll
        for (int j = 0; j < 2; j++) {
            FragB bh;
            wmma::load_matrix_sync(bh, sB_ + (wn + j*16)*LDA16, LDA16);
            #pragma unroll
            for (int i = 0; i < 4; i++)
                wmma::mma_sync(acc[i][j], ah[i], bh, acc[i][j]);
        }
    }
    __syncthreads();
    #pragma unroll
    for (int i = 0; i < 4; i++)
        #pragma unroll
        for (int j = 0; j < 2; j++)
            wmma::store_matrix_sync(stage + (wm + i*16)*LDS + wn + j*16,
                                    acc[i][j], LDS, wmma::mem_row_major);
    __syncthreads();
}

// ============== Y = Xhi (Aophi+Aoplo)^T, output bf16 hi ==============
__global__ __launch_bounds__(256, 2) void y_mma_kernel() {
    extern __shared__ char sm[];
    float* stage = (float*)sm;
    int n0 = blockIdx.x*128, m0 = blockIdx.y*128;
    int tid = threadIdx.x;

    mma_tile_pre2(g_Xhi + (size_t)m0*HH, HH,
                  g_Aophi + (size_t)n0*HH, g_Aoplo + (size_t)n0*HH, HH,
                  sm, stage);

    int c = tid & 127, rr = tid >> 7;
    for (int r2 = rr; r2 < 128; r2 += 2)
        g_Yhi[(size_t)(m0 + r2)*HH + n0 + c] = __float2bfloat16(stage[r2*LDS + c]);
}

// ============== attention: sigmoid((Yhi.Xhi + c1 + c2 + c0)*s) sums ==========
__global__ __launch_bounds__(256, 2) void attn_mma_kernel() {
    extern __shared__ char sm[];
    float* stage = (float*)sm;
    __shared__ float c1row[128];
    int b  = blockIdx.z;
    int n0 = blockIdx.x * 128;
    int m0 = blockIdx.y * 128;
    int tid = threadIdx.x;

    mma_tile_pre1(g_Yhi + ((size_t)m0*BB + b)*HH, (size_t)BB*HH,
                  g_Xhi + ((size_t)n0*BB + b)*HH, (size_t)BB*HH,
                  sm, stage);

    if (tid < 128) c1row[tid] = g_c1[(m0 + tid)*BB + b];
    __syncthreads();

    const float scale = 0.04419417382415922f;  // 512^-0.5
    if (tid < 128) {
        float c2v = g_c2[(n0 + tid)*BB + b] + g_cc[0];
        float s = 0.f;
        #pragma unroll 4
        for (int rr = 0; rr < 128; rr++) {
            float lg = stage[rr*LDS + tid] + c1row[rr] + c2v;
            s += 1.0f / (1.0f + __expf(-lg*scale));
        }
        g_wpart[blockIdx.y*(BB*TT) + b*TT + n0 + tid] = s;
    }
}

// ============== tails ==============
__global__ void reduce_w_kernel() {
    int i = blockIdx.x*256 + threadIdx.x;
    g_wsum[i] = g_wpart[i] + g_wpart[BB*TT + i]
              + g_wpart[2*BB*TT + i] + g_wpart[3*BB*TT + i];
}

__global__ __launch_bounds__(128) void zsum_kernel() {
    int kq = blockIdx.x, b = blockIdx.y;
    int k = kq*128 + threadIdx.x;
    float acc = 0.f, sw = 0.f;
    const float* wrow = g_wsum + b*TT;
    #pragma unroll 4
    for (int s = 0; s < TT; s++) {
        float w = wrow[s];
        sw += w;
        size_t idx = ((size_t)s*BB + b)*HH + k;
        float xv = __bfloat162float(g_Xhi[idx]) + __bfloat162float(g_Xlo[idx]);
        acc += w * xv;
    }
    g_z[b*HH + k] = acc;
    if (kq == 0 && threadIdx.x == 0) g_sw[b] = sw;
}

__global__ __launch_bounds__(128) void featw_kernel(
        const float* __restrict__ wv, const float* __restrict__ bv) {
    __shared__ float zs[HH];
    int b = blockIdx.y;
    int d = blockIdx.x*128 + threadIdx.x;
    for (int i = threadIdx.x; i < HH; i += 128) zs[i] = g_z[b*HH + i];
    __syncthreads();
    const float* wr = wv + (size_t)d*HH;
    float acc = 0.f;
    #pragma unroll 4
    for (int k = 0; k < HH; k++) acc += zs[k] * wr[k];
    g_feat[b*HH + d] = (acc + g_sw[b]*bv[d]) * (1.0f/TT);
}

__global__ void feat_bn_kernel(const float* __restrict__ g,
                               const float* __restrict__ bb) {
    int d = threadIdx.x;
    float s = 0.f, sq = 0.f;
    for (int b = 0; b < BB; b++) {
        float v = g_feat[b*HH + d];
        s += v; sq += v*v;
    }
    float m = s * (1.0f/BB);
    float rstd = rsqrtf(sq*(1.0f/BB) - m*m + 1e-5f);
    float gg = g[d]*rstd;
    float bo = bb[d] - m*gg;
    for (int b = 0; b < BB; b++)
        g_featn[b*HH + d] = g_feat[b*HH + d]*gg + bo;
}

__global__ void final_lin_kernel(const float* __restrict__ wh,
                                 const float* __restrict__ bh,
                                 float* __restrict__ out) {
    __shared__ float fs[HH];
    int b = blockIdx.x;
    int o = threadIdx.x;
    for (int i = o; i < HH; i += 96) fs[i] = g_featn[b*HH + i];
    __syncthreads();
    float acc = bh[o];
    for (int d = 0; d < HH; d++) acc += fs[d] * wh[o*HH + d];
    out[b*HORZ + o] = acc;
}

// ---------------- launch ------------------------------------------------------
extern "C" void kernel_launch(void* const* d_in, const int* in_sizes, int n_in,
                              void* d_out, int out_size) {
    const float* x        = (const float*)d_in[0];
    const float* conv_w   = (const float*)d_in[1];
    const float* conv_b   = (const float*)d_in[2];
    const float* bn1_g    = (const float*)d_in[3];
    const float* bn1_b    = (const float*)d_in[4];
    const float* beta_enc = (const float*)d_in[5];
    const float* bn2_g    = (const float*)d_in[6];
    const float* bn2_b    = (const float*)d_in[7];
    const float* beta2    = (const float*)d_in[8];
    const float* bn3_g    = (const float*)d_in[9];
    const float* bn3_b    = (const float*)d_in[10];
    const float* beta3    = (const float*)d_in[11];
    const float* wq       = (const float*)d_in[12];
    const float* bq       = (const float*)d_in[13];
    const float* wk       = (const float*)d_in[14];
    const float* bk       = (const float*)d_in[15];
    const float* wv       = (const float*)d_in[16];
    const float* bv       = (const float*)d_in[17];
    const float* bna_g    = (const float*)d_in[18];
    const float* bna_b    = (const float*)d_in[19];
    const float* wh       = (const float*)d_in[20];
    const float* bh       = (const float*)d_in[21];
    float* out = (float*)d_out;

    cudaFuncSetAttribute(y_mma_kernel,    cudaFuncAttributeMaxDynamicSharedMemorySize, SM_DYN);
    cudaFuncSetAttribute(attn_mma_kernel, cudaFuncAttributeMaxDynamicSharedMemorySize, SM_DYN);

    prep_uwc_kernel<<<4, 128>>>(wq, bk, wk, bq);
    aop_kernel<<<dim3(4, 32), 128>>>(wq, wk);

    conv_kernel<<<dim3(NCHN/16, BB), 128>>>(x, conv_w, conv_b);
    chan_stats_kernel<<<NCHN, 256>>>();
    bn1t_kernel<<<dim3(NCHN, 4), 128>>>(bn1_g, bn1_b);

    snn_fused_kernel<<<HH, 128>>>(beta_enc, bn2_g, bn2_b, beta2, bn3_g, bn3_b, beta3);

    xpose_kernel<<<dim3(TT, 16), 256>>>();
    c12red_kernel<<<(TT*BB)/256, 256>>>();

    y_mma_kernel<<<dim3(4, TT), 256, SM_DYN>>>();
    attn_mma_kernel<<<dim3(TT/128, TT/128, BB), 256, SM_DYN>>>();

    reduce_w_kernel<<<(BB*TT)/256, 256>>>();
    zsum_kernel<<<dim3(4, BB), 128>>>();
    featw_kernel<<<dim3(4, BB), 128>>>(wv, bv);
    feat_bn_kernel<<<1, HH>>>(bna_g, bna_b);
    final_lin_kernel<<<BB, HORZ>>>(wh, bh, out);
}